// round 17
// baseline (speedup 1.0000x reference)
#include <cuda_runtime.h>
#include <cuda_fp16.h>
#include <cstdint>

#define NN   2048
#define CDIM 256
#define MS   8          // m splits (blockIdx.y)
#define PAD  264        // fp16 elems per smem row (padded); 528 B row stride

__device__ float    g_Z[2][NN * CDIM];
__device__ __half   g_Zh[NN * CDIM];             // fp16 high part of current Z
__device__ __half   g_part[MS][NN * CDIM];       // per m-split partials (fp16)
__device__ unsigned g_maskbits[NN * (NN / 32)];  // word[n*64+mw], bit = m&31

// smem layout (bytes): block = 32n x 256m-tilechain
#define OFF_ZN   0                               // Zn fp16: 32 x PAD
#define OFF_ZM   (32 * PAD * 2)                  // 16896; 2 buffers
#define ZMBUF    (32 * PAD * 2)                  // 16896
#define SM_TOTAL (OFF_ZM + 2 * ZMBUF)            // 50688
#define CPAD     264                             // combine stride (floats)

__device__ __forceinline__ uint32_t smem_u32(const void* p) {
    uint32_t a;
    asm("{ .reg .u64 t; cvta.to.shared.u64 t, %1; cvt.u32.u64 %0, t; }" : "=r"(a) : "l"(p));
    return a;
}
__device__ __forceinline__ uint32_t packh(float x0, float x1) {
    __half2 hp = __floats2half2_rn(x0, x1);
    return *(uint32_t*)&hp;
}

#define LDSM4(r, a) asm volatile( \
    "ldmatrix.sync.aligned.m8n8.x4.shared.b16 {%0,%1,%2,%3}, [%4];" \
    : "=r"((r)[0]), "=r"((r)[1]), "=r"((r)[2]), "=r"((r)[3]) : "r"(a))
#define LDSM4T(r, a) asm volatile( \
    "ldmatrix.sync.aligned.m8n8.x4.trans.shared.b16 {%0,%1,%2,%3}, [%4];" \
    : "=r"((r)[0]), "=r"((r)[1]), "=r"((r)[2]), "=r"((r)[3]) : "r"(a))
#define MMA(d, a, b0, b1) asm volatile( \
    "mma.sync.aligned.m16n8k16.row.col.f32.f16.f16.f32 " \
    "{%0,%1,%2,%3}, {%4,%5,%6,%7}, {%8,%9}, {%0,%1,%2,%3};" \
    : "+f"((d)[0]), "+f"((d)[1]), "+f"((d)[2]), "+f"((d)[3]) \
    : "r"((a)[0]), "r"((a)[1]), "r"((a)[2]), "r"((a)[3]), "r"(b0), "r"(b1))

// ---------------- pack adjacency bits [n][mword] ----------------
__global__ void pack_mask_kernel(const int* __restrict__ adj) {
    int wIdx = blockIdx.x * 256 + threadIdx.x;
    const int4* p = ((const int4*)adj) + (size_t)wIdx * 8;
    unsigned bits = 0;
#pragma unroll
    for (int j = 0; j < 8; j++) {
        int4 v = p[j];
        if (v.x > 0) bits |= 1u << (4 * j + 0);
        if (v.y > 0) bits |= 1u << (4 * j + 1);
        if (v.z > 0) bits |= 1u << (4 * j + 2);
        if (v.w > 0) bits |= 1u << (4 * j + 3);
    }
    g_maskbits[wIdx] = bits;
}

// ---------------- projection + per-channel L2 norm (fp32 + fp16 out) ----------------
__global__ void proj_kernel(const float* __restrict__ feat,
                            const float* __restrict__ W,
                            const float* __restrict__ b) {
    __shared__ float fs[128];
    int n = blockIdx.x, t = threadIdx.x;
    if (t < 128) fs[t] = feat[n * 128 + t];
    __syncthreads();
    int k = t >> 5, d = t & 31;
    const float* Wp = W + k * 4096 + d;
    float s = b[t];
#pragma unroll 16
    for (int i = 0; i < 128; i++) s = fmaf(fs[i], Wp[i * 32], s);
    float ss = s * s;
#pragma unroll
    for (int o = 16; o; o >>= 1) ss += __shfl_xor_sync(0xffffffffu, ss, o);
    float inv = 1.0f / fmaxf(sqrtf(ss), 1e-12f);
    float r = s * inv;
    g_Z[0][(size_t)n * CDIM + t] = r;
    g_Zh[(size_t)n * CDIM + t] = __float2half_rn(r);
}

// ---------------- fused iteration (R11/R16 structure + mask prefetch) ----------------
// block: 32 n x 256 m; 4 warps = 2 n-blocks(16) x 2 m-halves(128); 2 blocks/SM
__global__ __launch_bounds__(128, 2) void iter_kernel(int unused) {
    extern __shared__ char smem[];
    uint32_t sb = smem_u32(smem);
    int t = threadIdx.x, w = t >> 5, lane = t & 31;
    int nb = w & 1, mh = w >> 1;
    int g = lane >> 2, tig = lane & 3;
    int n0 = blockIdx.x * 32, mbase = blockIdx.y * (NN / MS);

    // ---- fill Zn (32 x 256 fp16): pure uint4 copy ----
#pragma unroll
    for (int it = 0; it < 8; it++) {
        int idx = t + it * 128;
        int n = idx >> 5, c4 = idx & 31;
        uint4 v = ((const uint4*)(g_Zh + (size_t)(n0 + n) * CDIM))[c4];
        *(uint4*)(smem + OFF_ZN + n * (PAD * 2) + c4 * 16) = v;
    }
    // fill Zm tile 0 into buffer 0
#pragma unroll
    for (int it = 0; it < 8; it++) {
        int idx = t + it * 128;
        int m = idx >> 5, c4 = idx & 31;
        uint4 v = ((const uint4*)(g_Zh + (size_t)(mbase + m) * CDIM))[c4];
        *(uint4*)(smem + OFF_ZM + m * (PAD * 2) + c4 * 16) = v;
    }
    __syncthreads();

    uint32_t aoffA = (uint32_t)(((nb * 16 + (lane & 15)) * PAD + ((lane >> 4) << 3)) * 2);
    uint32_t boffA = (uint32_t)(((mh * 16 + ((lane >> 4) << 3) + (lane & 7)) * PAD +
                                 (((lane >> 3) & 1) << 3)) * 2);
    uint32_t boffT = (uint32_t)(((mh * 16 + (((lane >> 3) & 1) << 3) + (lane & 7)) * PAD +
                                 ((lane >> 4) << 3)) * 2);
    int nA = n0 + nb * 16 + g;

    float C[8][4][4];
#pragma unroll
    for (int c = 0; c < 8; c++)
#pragma unroll
        for (int q = 0; q < 4; q++) { C[c][q][0] = C[c][q][1] = C[c][q][2] = C[c][q][3] = 0.f; }

    // mask words for tile 0 (prefetched ahead of each tile thereafter)
    unsigned wA = g_maskbits[(size_t)nA * 64 + (mbase >> 5)];
    unsigned wB = g_maskbits[(size_t)(nA + 8) * 64 + (mbase >> 5)];

    for (int mt = 0; mt < 8; mt++) {
        int m0 = mbase + mt * 32;
        uint32_t bufc = OFF_ZM + (uint32_t)(mt & 1) * ZMBUF;

        // ---- prefetch next Zm tile + next mask words (overlap compute) ----
        unsigned nwA = 0, nwB = 0;
        if (mt < 7) {
            uint32_t bufn = OFF_ZM + (uint32_t)((mt + 1) & 1) * ZMBUF;
            int m1 = m0 + 32;
#pragma unroll
            for (int it = 0; it < 8; it++) {
                int idx = t + it * 128;
                int m = idx >> 5, c4 = idx & 31;
                uint4 v = ((const uint4*)(g_Zh + (size_t)(m1 + m) * CDIM))[c4];
                *(uint4*)(smem + bufn + m * (PAD * 2) + c4 * 16) = v;
            }
            nwA = g_maskbits[(size_t)nA * 64 + (m1 >> 5)];
            nwB = g_maskbits[(size_t)(nA + 8) * 64 + (m1 >> 5)];
        }

        // ---- Phase A: S = ZnH . ZmH^T (single fp16 term) ----
        float S[8][2][4];
#pragma unroll
        for (int c = 0; c < 8; c++)
#pragma unroll
            for (int ms = 0; ms < 2; ms++) { S[c][ms][0] = S[c][ms][1] = S[c][ms][2] = S[c][ms][3] = 0.f; }
#pragma unroll
        for (int ch = 0; ch < 8; ch++) {
#pragma unroll
            for (int ks = 0; ks < 2; ks++) {
                uint32_t kb2 = (uint32_t)(ch * 32 + ks * 16) * 2;
                uint32_t aH[4], bH[4];
                LDSM4(aH, sb + OFF_ZN + aoffA + kb2);
                LDSM4(bH, sb + bufc + boffA + kb2);
                MMA(S[ch][0], aH, bH[0], bH[1]);
                MMA(S[ch][1], aH, bH[2], bH[3]);
            }
        }

        // ---- softmax over channels (in-lane) ----
        float sum[2][4];
#pragma unroll
        for (int ms = 0; ms < 2; ms++)
#pragma unroll
            for (int q = 0; q < 4; q++) sum[ms][q] = 0.f;
#pragma unroll
        for (int ch = 0; ch < 8; ch++)
#pragma unroll
            for (int ms = 0; ms < 2; ms++)
#pragma unroll
                for (int q = 0; q < 4; q++) {
                    float e = __expf(S[ch][ms][q]);   // |s|<=1
                    S[ch][ms][q] = e; sum[ms][q] += e;
                }
        float inv[2][4];
#pragma unroll
        for (int ms = 0; ms < 2; ms++)
#pragma unroll
            for (int q = 0; q < 4; q++) {
                int bitpos = mh * 16 + ms * 8 + 2 * tig + (q & 1);
                unsigned wd = (q >> 1) ? wB : wA;
                inv[ms][q] = ((wd >> bitpos) & 1u) ? __fdividef(1.f, sum[ms][q]) : 0.f;
            }
        uint32_t attH[8][4];
#pragma unroll
        for (int ch = 0; ch < 8; ch++)
#pragma unroll
            for (int ms = 0; ms < 2; ms++) {
                attH[ch][ms * 2]     = packh(S[ch][ms][0] * inv[ms][0], S[ch][ms][1] * inv[ms][1]);
                attH[ch][ms * 2 + 1] = packh(S[ch][ms][2] * inv[ms][2], S[ch][ms][3] * inv[ms][3]);
            }

        // ---- Phase B: C += attH . ZmH (single term) ----
#pragma unroll
        for (int ch = 0; ch < 8; ch++) {
            uint32_t d0 = (uint32_t)(ch * 32) * 2, d1 = (uint32_t)(ch * 32 + 16) * 2;
            uint32_t bh0[4], bh1[4];
            LDSM4T(bh0, sb + bufc + boffT + d0);
            LDSM4T(bh1, sb + bufc + boffT + d1);
            MMA(C[ch][0], attH[ch], bh0[0], bh0[1]);
            MMA(C[ch][1], attH[ch], bh0[2], bh0[3]);
            MMA(C[ch][2], attH[ch], bh1[0], bh1[1]);
            MMA(C[ch][3], attH[ch], bh1[2], bh1[3]);
        }
        wA = nwA; wB = nwB;
        __syncthreads();
    }

    // ---- combine m-halves in smem (overlays dead buffers), write fp16 g_part ----
    float* comb = (float*)smem;
    if (mh == 1) {
        int nl = nb * 16 + g;
#pragma unroll
        for (int ch = 0; ch < 8; ch++)
#pragma unroll
            for (int db = 0; db < 4; db++) {
                int d = ch * 32 + db * 8 + 2 * tig;
                *(float2*)&comb[(size_t)nl * CPAD + d]       = make_float2(C[ch][db][0], C[ch][db][1]);
                *(float2*)&comb[(size_t)(nl + 8) * CPAD + d] = make_float2(C[ch][db][2], C[ch][db][3]);
            }
    }
    __syncthreads();
    if (mh == 0) {
        int nl = nb * 16 + g;
        __half* dst = g_part[blockIdx.y];
#pragma unroll
        for (int ch = 0; ch < 8; ch++)
#pragma unroll
            for (int db = 0; db < 4; db++) {
                int d = ch * 32 + db * 8 + 2 * tig;
                float2 o0 = *(float2*)&comb[(size_t)nl * CPAD + d];
                float2 o1 = *(float2*)&comb[(size_t)(nl + 8) * CPAD + d];
                *(__half2*)&dst[(size_t)nA * CDIM + d] =
                    __floats2half2_rn(C[ch][db][0] + o0.x, C[ch][db][1] + o0.y);
                *(__half2*)&dst[(size_t)(nA + 8) * CDIM + d] =
                    __floats2half2_rn(C[ch][db][2] + o1.x, C[ch][db][3] + o1.y);
            }
    }
}

// ---------------- vectorized residual + sum partials + per-channel L2 norm ----------------
// warp per row: lane owns 8 consecutive cols (one channel per 4-lane group)
__global__ void norm_kernel(int zi, int zo, float* __restrict__ outp) {
    int w = threadIdx.x >> 5, lane = threadIdx.x & 31;
    int n = blockIdx.x * 8 + w;
    size_t base = (size_t)n * CDIM + lane * 8;

    float4 a = *(const float4*)&g_Z[zi][base];
    float4 b = *(const float4*)&g_Z[zi][base + 4];
#pragma unroll
    for (int s = 0; s < MS; s++) {
        uint4 p = *(const uint4*)&g_part[s][base];      // 8 halves
        const __half2* ph = (const __half2*)&p;
        float2 f0 = __half22float2(ph[0]);
        float2 f1 = __half22float2(ph[1]);
        float2 f2 = __half22float2(ph[2]);
        float2 f3 = __half22float2(ph[3]);
        a.x += f0.x; a.y += f0.y; a.z += f1.x; a.w += f1.y;
        b.x += f2.x; b.y += f2.y; b.z += f3.x; b.w += f3.y;
    }
    float ss = a.x * a.x + a.y * a.y + a.z * a.z + a.w * a.w
             + b.x * b.x + b.y * b.y + b.z * b.z + b.w * b.w;
    // per-channel (32-col) reduction: 4-lane group
    ss += __shfl_xor_sync(0xffffffffu, ss, 2);
    ss += __shfl_xor_sync(0xffffffffu, ss, 1);
    float inv = 1.0f / fmaxf(sqrtf(ss), 1e-12f);
    a.x *= inv; a.y *= inv; a.z *= inv; a.w *= inv;
    b.x *= inv; b.y *= inv; b.z *= inv; b.w *= inv;
    if (outp) {
        *(float4*)&outp[base] = a;
        *(float4*)&outp[base + 4] = b;
    } else {
        *(float4*)&g_Z[zo][base] = a;
        *(float4*)&g_Z[zo][base + 4] = b;
        uint4 hout;
        ((__half2*)&hout)[0] = __floats2half2_rn(a.x, a.y);
        ((__half2*)&hout)[1] = __floats2half2_rn(a.z, a.w);
        ((__half2*)&hout)[2] = __floats2half2_rn(b.x, b.y);
        ((__half2*)&hout)[3] = __floats2half2_rn(b.z, b.w);
        *(uint4*)&g_Zh[base] = hout;
    }
}

extern "C" void kernel_launch(void* const* d_in, const int* in_sizes, int n_in,
                              void* d_out, int out_size) {
    const int* adj = nullptr; const float* feat = nullptr;
    const float* W = nullptr; const float* b = nullptr;
    for (int i = 0; i < n_in; i++) {
        switch (in_sizes[i]) {
            case NN * NN:      adj  = (const int*)d_in[i];   break;
            case NN * 128:     feat = (const float*)d_in[i]; break;
            case 8 * 128 * 32: W    = (const float*)d_in[i]; break;
            case 256:          b    = (const float*)d_in[i]; break;
        }
    }
    float* out = (float*)d_out;

    cudaFuncSetAttribute(iter_kernel, cudaFuncAttributeMaxDynamicSharedMemorySize, SM_TOTAL);

    pack_mask_kernel<<<NN * (NN / 32) / 256, 256>>>(adj);
    proj_kernel<<<NN, 256>>>(feat, W, b);

    int cur = 0;
    for (int it = 0; it < 4; it++) {
        dim3 grid(NN / 32, MS);
        iter_kernel<<<grid, 128, SM_TOTAL>>>(0);
        norm_kernel<<<NN / 8, 256>>>(cur, cur ^ 1, (it == 3) ? out : nullptr);
        cur ^= 1;
    }
}